// round 12
// baseline (speedup 1.0000x reference)
#include <cuda_runtime.h>

typedef unsigned long long u64;
typedef unsigned int u32;

#define NB      16
#define SS      4096
#define ROWB    2048         // gmem/staging row bytes (fp32)
#define RROWB   1024         // ring row bytes (bf16)
#define HALO    19
#define CHUNK   16
#define RING    51           // 2*CHUNK + HALO
#define RINGB   (RING * RROWB)      // 52224
#define STGB    (CHUNK * ROWB)      // 32768
#define MBAROFF (RINGB + STGB)      // 84992
#define SMEMSZ  (MBAROFF + 16)
#define TM      2
#define NWARPS  8
#define NTHR    256
#define NSEG    18
#define SEGROWS 228          // 17 segs of 228 + last 220 = 4096
#define NBLK    (NB * NSEG)  // 288
#define CNT_DIST 40815       // sum_{k=10}^{19} (4096 - k)

__device__ float2       g_part[NBLK];
__device__ unsigned int g_count = 0;

__device__ __forceinline__ u64 ffma2(u64 a, u64 b, u64 c) {
    u64 d;
    asm("fma.rn.f32x2 %0, %1, %2, %3;" : "=l"(d) : "l"(a), "l"(b), "l"(c));
    return d;
}
__device__ __forceinline__ u64 fmul2(u64 a, u64 b) {
    u64 d;
    asm("mul.rn.f32x2 %0, %1, %2;" : "=l"(d) : "l"(a), "l"(b));
    return d;
}
__device__ __forceinline__ u64 fadd2(u64 a, u64 b) {
    u64 d;
    asm("add.rn.f32x2 %0, %1, %2;" : "=l"(d) : "l"(a), "l"(b));
    return d;
}
__device__ __forceinline__ u64 pack2(float x, float y) {
    u64 d;
    asm("mov.b64 %0, {%1, %2};" : "=l"(d) : "f"(x), "f"(y));
    return d;
}
__device__ __forceinline__ float hsum2(u64 v) {
    float x, y;
    asm("mov.b64 {%0,%1}, %2;" : "=f"(x), "=f"(y) : "l"(v));
    return x + y;
}
// bf16x2 fused multiply-add, packed 2-wide, bf16 accumulate
__device__ __forceinline__ u32 hfma2b(u32 a, u32 b, u32 c) {
    u32 d;
    asm("fma.rn.bf16x2 %0, %1, %2, %3;" : "=r"(d) : "r"(a), "r"(b), "r"(c));
    return d;
}
// bf16x2 accumulator -> fp32 (hi + lo); bf16 is fp32's upper 16 bits
__device__ __forceinline__ float extbf(u32 acc) {
    float hi = __uint_as_float(acc & 0xFFFF0000u);
    float lo = __uint_as_float(acc << 16);
    return hi + lo;
}
// two fp32 -> packed bf16x2 (hi_src -> bits[31:16], lo_src -> bits[15:0])
__device__ __forceinline__ u32 cvt2(float hi_src, float lo_src) {
    u32 d;
    asm("cvt.rn.bf16x2.f32 %0, %1, %2;" : "=r"(d) : "f"(hi_src), "f"(lo_src));
    return d;
}
__device__ __forceinline__ void unpk2(u64 v, float& a, float& b) {
    asm("mov.b64 {%0, %1}, %2;" : "=f"(a), "=f"(b) : "l"(v));
}
__device__ __forceinline__ float wred(float v) {
    v += __shfl_xor_sync(0xffffffffu, v, 16);
    v += __shfl_xor_sync(0xffffffffu, v, 8);
    v += __shfl_xor_sync(0xffffffffu, v, 4);
    v += __shfl_xor_sync(0xffffffffu, v, 2);
    v += __shfl_xor_sync(0xffffffffu, v, 1);
    return v;
}
// Batched butterfly: reduce 4 per-lane partials across the warp with 6 shfl.
// Result: lane octet g (lane>>3) holds the warp total of v_g (replicated 8x).
__device__ __forceinline__ float bfly4(float v0, float v1, float v2, float v3,
                                       int lane) {
    const bool hi16 = (lane & 16) != 0;
    const bool hi8  = (lane & 8)  != 0;
    float a  = hi16 ? v0 : v2;
    float ra = __shfl_xor_sync(0xffffffffu, a, 16);
    float x  = (hi16 ? v2 : v0) + ra;
    float bb = hi16 ? v1 : v3;
    float rb = __shfl_xor_sync(0xffffffffu, bb, 16);
    float y  = (hi16 ? v3 : v1) + rb;
    float c  = hi8 ? x : y;
    float rc = __shfl_xor_sync(0xffffffffu, c, 8);
    float z  = (hi8 ? y : x) + rc;
    z += __shfl_xor_sync(0xffffffffu, z, 4);
    z += __shfl_xor_sync(0xffffffffu, z, 2);
    z += __shfl_xor_sync(0xffffffffu, z, 1);
    return z;
}
__device__ __forceinline__ u32 smem_u32(const void* p) {
    u32 a;
    asm("{ .reg .u64 t; cvta.to.shared.u64 t, %1; cvt.u32.u64 %0, t; }"
        : "=r"(a) : "l"(p));
    return a;
}
__device__ __forceinline__ void mbar_init(u32 mbar, u32 cnt) {
    asm volatile("mbarrier.init.shared.b64 [%0], %1;" :: "r"(mbar), "r"(cnt) : "memory");
}
__device__ __forceinline__ void mbar_expect(u32 mbar, u32 bytes) {
    asm volatile("mbarrier.arrive.expect_tx.shared.b64 _, [%0], %1;"
                 :: "r"(mbar), "r"(bytes) : "memory");
}
__device__ __forceinline__ void bulk_g2s(u32 dst, const void* src, u32 bytes, u32 mbar) {
    asm volatile("cp.async.bulk.shared::cta.global.mbarrier::complete_tx::bytes "
                 "[%0], [%1], %2, [%3];"
                 :: "r"(dst), "l"(src), "r"(bytes), "r"(mbar) : "memory");
}
__device__ __forceinline__ void mbar_wait(u32 mbar, u32 parity) {
    asm volatile(
        "{\n\t.reg .pred P;\n"
        "W%=:\n\t"
        "mbarrier.try_wait.parity.acquire.cta.shared::cta.b64 P, [%0], %1, 0x989680;\n\t"
        "@P bra D%=;\n\t"
        "bra W%=;\n"
        "D%=:\n\t}"
        :: "r"(mbar), "r"(parity) : "memory");
}

extern __shared__ char smemc[];  // [ring bf16 | staging fp32 | mbar]

// read one fp32 row from staging, normalize (fp32), write bf16 row into ring.
// ring row layout: group g (=0..3) at bytes [256g,256g+256); lane l writes
// 8 bytes (elements 4l..4l+3 of that group's 128-element span) at 256g + 8l.
__device__ __forceinline__ void norm_convert(const ulonglong2* stg_row,
                                             char* ring_row, int lane) {
    ulonglong2 v0 = stg_row[lane];
    ulonglong2 v1 = stg_row[lane + 32];
    ulonglong2 v2 = stg_row[lane + 64];
    ulonglong2 v3 = stg_row[lane + 96];
    u64 p0 = 0ull, p1 = 0ull, p2 = 0ull, p3 = 0ull;
    p0 = ffma2(v0.x, v0.x, p0); p1 = ffma2(v0.y, v0.y, p1);
    p2 = ffma2(v1.x, v1.x, p2); p3 = ffma2(v1.y, v1.y, p3);
    p0 = ffma2(v2.x, v2.x, p0); p1 = ffma2(v2.y, v2.y, p1);
    p2 = ffma2(v3.x, v3.x, p2); p3 = ffma2(v3.y, v3.y, p3);
    float s    = wred(hsum2(fadd2(fadd2(p0, p1), fadd2(p2, p3))));
    float invn = rsqrtf(s);
    u64 iv = pack2(invn, invn);

    ulonglong2 vg[4] = {v0, v1, v2, v3};
#pragma unroll
    for (int g = 0; g < 4; ++g) {
        u64 sx = fmul2(vg[g].x, iv);
        u64 sy = fmul2(vg[g].y, iv);
        float f0, f1, f2, f3;
        unpk2(sx, f0, f1);
        unpk2(sy, f2, f3);
        uint2 cc;
        cc.x = cvt2(f1, f0);
        cc.y = cvt2(f3, f2);
        *reinterpret_cast<uint2*>(ring_row + (g << 8) + (lane << 3)) = cc;
    }
}

// pair j -> partner distance d (j enumerates (d, ii) in the fixed order)
__device__ __forceinline__ int pair_d(int j) {
    return (j == 0) ? 10 : ((j == 19) ? 20 : (10 + ((j + 1) >> 1)));
}

__global__ void __launch_bounds__(NTHR, 2)
tcl_main(const float* __restrict__ hs, float* __restrict__ out) {
    const int seg  = blockIdx.x;
    const int b    = blockIdx.y;
    const int t0   = seg * SEGROWS;
    const int tEnd = (t0 + SEGROWS < SS) ? (t0 + SEGROWS) : SS;
    const int rEnd = (tEnd + HALO < SS) ? (tEnd + HALO) : SS;   // rows needed
    const int tid  = threadIdx.x;
    const int wid  = tid >> 5;
    const int lane = tid & 31;

    char* ring = smemc;
    const ulonglong2* stg = reinterpret_cast<const ulonglong2*>(smemc + RINGB);
    const char* gbase = reinterpret_cast<const char*>(hs) + (size_t)b * SS * ROWB;
    const u32 sbase = smem_u32(smemc);
    const u32 stgb  = sbase + RINGB;
    const u32 mbar  = sbase + MBAROFF;

    // ── prologue: staged copies of the first RING rows, convert to bf16 ──
    if (tid == 0) {
        mbar_init(mbar, 1);
        asm volatile("fence.proxy.async.shared::cta;" ::: "memory");
    }
    __syncthreads();

    int cid = 0;                                    // copy counter (parity)
    const int ringEnd = (t0 + RING < rEnd) ? (t0 + RING) : rEnd;
    {
        int ps = t0;
        int pe = (ps + CHUNK < ringEnd) ? (ps + CHUNK) : ringEnd;
        if (tid == 0) {
            mbar_expect(mbar, (u32)(pe - ps) * ROWB);
            bulk_g2s(stgb, gbase + (size_t)ps * ROWB, (u32)(pe - ps) * ROWB, mbar);
        }
        while (true) {
            mbar_wait(mbar, (u32)(cid & 1));
            cid++;
            for (int r = ps + wid; r < pe; r += NWARPS)
                norm_convert(stg + (size_t)(r - ps) * 128,
                             ring + (size_t)((r - t0) % RING) * RROWB, lane);
            __syncthreads();                        // staging consumed
            int ns = pe;
            int ne = (ns + CHUNK < ringEnd) ? (ns + CHUNK) : ringEnd;
            if (ns >= ne) break;
            if (tid == 0) {
                mbar_expect(mbar, (u32)(ne - ns) * ROWB);
                bulk_g2s(stgb, gbase + (size_t)ns * ROWB, (u32)(ne - ns) * ROWB, mbar);
            }
            ps = ns; pe = ne;
        }
    }
    __syncthreads();

    float accA = 0.f;   // adjacent sum (per-lane fp32 partials)
    float accD = 0.f;   // distant relu sum (octet-replicated)

    const int nsteps = (tEnd - t0 + CHUNK - 1) / CHUNK;

    for (int i = 0; i < nsteps; ++i) {
        const int c0     = t0 + CHUNK * i;
        const int rowEnd = (c0 + CHUNK < tEnd) ? (c0 + CHUNK) : tEnd;
        const int tt     = c0 + wid * TM;

        // ── Phase B: pairs for this 16-row chunk (8 warps × 2 rows) ─────
        if (tt < rowEnd) {                       // warp-uniform; tiles 2-aligned
            int sb = (tt - t0) % RING;

            uint4 A[TM][2];
#pragma unroll
            for (int ii = 0; ii < TM; ++ii) {
                int sl = sb + ii; if (sl >= RING) sl -= RING;
                const uint4* rp = reinterpret_cast<const uint4*>(
                    ring + (size_t)sl * RROWB);
                A[ii][0] = rp[lane];
                A[ii][1] = rp[lane + 32];
            }

            // adjacent pair (tt, tt+1): both rows in registers
            {
                u32 acc = 0;
                acc = hfma2b(A[0][0].x, A[1][0].x, acc);
                acc = hfma2b(A[0][0].y, A[1][0].y, acc);
                acc = hfma2b(A[0][0].z, A[1][0].z, acc);
                acc = hfma2b(A[0][0].w, A[1][0].w, acc);
                acc = hfma2b(A[0][1].x, A[1][1].x, acc);
                acc = hfma2b(A[0][1].y, A[1][1].y, acc);
                acc = hfma2b(A[0][1].z, A[1][1].z, acc);
                acc = hfma2b(A[0][1].w, A[1][1].w, acc);
                accA += extbf(acc);
            }

            // adjacent pair (tt+1, tt+2): partner row d = 2 from smem
            {
                int r = tt + TM;
                if (r < rEnd) {
                    int sl = sb + TM; if (sl >= RING) sl -= RING;
                    const uint4* rp = reinterpret_cast<const uint4*>(
                        ring + (size_t)sl * RROWB);
                    uint4 S0 = rp[lane];
                    uint4 S1 = rp[lane + 32];
                    u32 acc = 0;
                    acc = hfma2b(A[1][0].x, S0.x, acc);
                    acc = hfma2b(A[1][0].y, S0.y, acc);
                    acc = hfma2b(A[1][0].z, S0.z, acc);
                    acc = hfma2b(A[1][0].w, S0.w, acc);
                    acc = hfma2b(A[1][1].x, S1.x, acc);
                    acc = hfma2b(A[1][1].y, S1.y, acc);
                    acc = hfma2b(A[1][1].z, S1.z, acc);
                    acc = hfma2b(A[1][1].w, S1.w, acc);
                    accA += extbf(acc);
                }
            }

            // distant pairs: 20 per-lane partial dots, then batched reduce
            float p[20];
#pragma unroll
            for (int j = 0; j < 20; ++j) p[j] = 0.f;

#pragma unroll
            for (int d = 10; d <= TM + HALO - 1; ++d) {
                int r = tt + d;
                if (r < rEnd) {                  // warp-uniform
                    int sl = sb + d; if (sl >= RING) sl -= RING;
                    const uint4* rp = reinterpret_cast<const uint4*>(
                        ring + (size_t)sl * RROWB);
                    uint4 S0 = rp[lane];
                    uint4 S1 = rp[lane + 32];
#pragma unroll
                    for (int ii = 0; ii < TM; ++ii) {
                        const int k = d - ii;
                        if (k >= 10 && k <= 19) {    // compile-time pruned
                            const int j = (d == 10) ? 0
                                        : ((d == 20) ? 19 : (2 * (d - 10) - 1 + ii));
                            u32 acc = 0;
                            acc = hfma2b(A[ii][0].x, S0.x, acc);
                            acc = hfma2b(A[ii][0].y, S0.y, acc);
                            acc = hfma2b(A[ii][0].z, S0.z, acc);
                            acc = hfma2b(A[ii][0].w, S0.w, acc);
                            acc = hfma2b(A[ii][1].x, S1.x, acc);
                            acc = hfma2b(A[ii][1].y, S1.y, acc);
                            acc = hfma2b(A[ii][1].z, S1.z, acc);
                            acc = hfma2b(A[ii][1].w, S1.w, acc);
                            p[j] = extbf(acc);
                        }
                    }
                }
            }

            // batched reductions: 5 groups of 4 pairs, 6 shfl each
#pragma unroll
            for (int g = 0; g < 5; ++g) {
                float z = bfly4(p[4*g], p[4*g+1], p[4*g+2], p[4*g+3], lane);
                int jme = 4 * g + (lane >> 3);
                int dme = pair_d(jme);
                float contrib = (tt + dme < rEnd) ? fmaxf(0.5f - z, 0.f) : 0.f;
                accD += contrib;
            }
        }

        // ── wait for copy C_i (issued last step), convert into ring ─────
        if (i >= 1) {
            int cs = t0 + (RING - CHUNK) + CHUNK * i;   // t0 + 35 + 16i
            if (cs < rEnd) {
                mbar_wait(mbar, (u32)(cid & 1));
                cid++;
                int ce = (cs + CHUNK < rEnd) ? (cs + CHUNK) : rEnd;
                for (int r = cs + wid; r < ce; r += NWARPS)
                    norm_convert(stg + (size_t)(r - cs) * 128,
                                 ring + (size_t)((r - t0) % RING) * RROWB, lane);
            }
        }
        __syncthreads();

        // ── issue copy C_{i+1} into staging (consumed next step) ────────
        if (tid == 0) {
            int ns = t0 + (RING - CHUNK) + CHUNK * (i + 1);
            if (ns < rEnd) {
                int ne = (ns + CHUNK < rEnd) ? (ns + CHUNK) : rEnd;
                u32 bytes = (u32)(ne - ns) * ROWB;
                mbar_expect(mbar, bytes);
                bulk_g2s(stgb, gbase + (size_t)ns * ROWB, bytes, mbar);
            }
        }
    }

    // ── block combine + grid ticket reduction ───────────────────────────
    float aWarp = wred(accA);
    float dWarp = wred(accD) * 0.125f;   // each pair counted by 8 lanes

    __shared__ float rA[NWARPS], rD[NWARPS];
    __shared__ int   sLast;
    if (lane == 0) { rA[wid] = aWarp; rD[wid] = dWarp; }
    __syncthreads();
    if (tid == 0) {
        float sA = 0.f, sD = 0.f;
#pragma unroll
        for (int w = 0; w < NWARPS; ++w) { sA += rA[w]; sD += rD[w]; }
        g_part[b * NSEG + seg] = make_float2(sA, sD);
        __threadfence();
        unsigned t = atomicAdd(&g_count, 1u);
        sLast = (t == NBLK - 1);
    }
    __syncthreads();

    if (sLast && tid < 32) {
        __threadfence();
        const float* gp = reinterpret_cast<const float*>(g_part);
        float a = 0.f, dd = 0.f;
        for (int i = tid; i < NBLK; i += 32) {
            a  += __ldcg(gp + 2 * i);
            dd += __ldcg(gp + 2 * i + 1);
        }
        a  = wred(a);
        dd = wred(dd);
        if (tid == 0) {
            float adj  = 1.f - a / ((float)NB * (float)(SS - 1));
            float dist = dd / ((float)NB * (float)CNT_DIST);
            out[0] = adj + dist;
            g_count = 0;                      // reset for next graph replay
        }
    }
}

extern "C" void kernel_launch(void* const* d_in, const int* in_sizes, int n_in,
                              void* d_out, int out_size) {
    (void)in_sizes; (void)n_in; (void)out_size;
    const float* hs = (const float*)d_in[0];

    cudaFuncSetAttribute(tcl_main, cudaFuncAttributeMaxDynamicSharedMemorySize,
                         SMEMSZ);

    dim3 grid(NSEG, NB);
    tcl_main<<<grid, NTHR, SMEMSZ>>>(hs, (float*)d_out);
}

// round 13
// speedup vs baseline: 1.0499x; 1.0499x over previous
#include <cuda_runtime.h>

typedef unsigned long long u64;
typedef unsigned int u32;

#define NB      16
#define SS      4096
#define ROWB    2048         // gmem/staging row bytes (fp32)
#define RROWB   1024         // ring row bytes (bf16)
#define HALO    19
#define CHUNK   48
#define RING    115          // 2*CHUNK + HALO
#define RINGB   (RING * RROWB)      // 117760
#define STGB    (CHUNK * ROWB)      // 98304
#define MBAROFF (RINGB + STGB)      // 216064
#define SMEMSZ  (MBAROFF + 16)
#define TM      2
#define NWARPS  24
#define NTHR    768
#define NSEG    9
#define SEGROWS 456          // 8 segs of 456 + last 448 = 4096
#define NBLK    (NB * NSEG)  // 144
#define CNT_DIST 40815       // sum_{k=10}^{19} (4096 - k)

__device__ float2       g_part[NBLK];
__device__ unsigned int g_count = 0;

__device__ __forceinline__ u64 ffma2(u64 a, u64 b, u64 c) {
    u64 d;
    asm("fma.rn.f32x2 %0, %1, %2, %3;" : "=l"(d) : "l"(a), "l"(b), "l"(c));
    return d;
}
__device__ __forceinline__ u64 fmul2(u64 a, u64 b) {
    u64 d;
    asm("mul.rn.f32x2 %0, %1, %2;" : "=l"(d) : "l"(a), "l"(b));
    return d;
}
__device__ __forceinline__ u64 fadd2(u64 a, u64 b) {
    u64 d;
    asm("add.rn.f32x2 %0, %1, %2;" : "=l"(d) : "l"(a), "l"(b));
    return d;
}
__device__ __forceinline__ u64 pack2(float x, float y) {
    u64 d;
    asm("mov.b64 %0, {%1, %2};" : "=l"(d) : "f"(x), "f"(y));
    return d;
}
__device__ __forceinline__ float hsum2(u64 v) {
    float x, y;
    asm("mov.b64 {%0,%1}, %2;" : "=f"(x), "=f"(y) : "l"(v));
    return x + y;
}
// bf16x2 fused multiply-add / add, packed 2-wide
__device__ __forceinline__ u32 hfma2b(u32 a, u32 b, u32 c) {
    u32 d;
    asm("fma.rn.bf16x2 %0, %1, %2, %3;" : "=r"(d) : "r"(a), "r"(b), "r"(c));
    return d;
}
__device__ __forceinline__ u32 hadd2b(u32 a, u32 b) {
    u32 d;
    asm("add.rn.bf16x2 %0, %1, %2;" : "=r"(d) : "r"(a), "r"(b));
    return d;
}
// bf16x2 accumulator -> fp32 (hi + lo)
__device__ __forceinline__ float extbf(u32 acc) {
    float hi = __uint_as_float(acc & 0xFFFF0000u);
    float lo = __uint_as_float(acc << 16);
    return hi + lo;
}
// two fp32 -> packed bf16x2
__device__ __forceinline__ u32 cvt2(float hi_src, float lo_src) {
    u32 d;
    asm("cvt.rn.bf16x2.f32 %0, %1, %2;" : "=r"(d) : "f"(hi_src), "f"(lo_src));
    return d;
}
__device__ __forceinline__ void unpk2(u64 v, float& a, float& b) {
    asm("mov.b64 {%0, %1}, %2;" : "=f"(a), "=f"(b) : "l"(v));
}
__device__ __forceinline__ float wred(float v) {
    v += __shfl_xor_sync(0xffffffffu, v, 16);
    v += __shfl_xor_sync(0xffffffffu, v, 8);
    v += __shfl_xor_sync(0xffffffffu, v, 4);
    v += __shfl_xor_sync(0xffffffffu, v, 2);
    v += __shfl_xor_sync(0xffffffffu, v, 1);
    return v;
}
// Batched butterfly: reduce 4 per-lane partials across the warp with 6 shfl.
// Result: lane octet g (lane>>3) holds the warp total of v_g (replicated 8x).
__device__ __forceinline__ float bfly4(float v0, float v1, float v2, float v3,
                                       int lane) {
    const bool hi16 = (lane & 16) != 0;
    const bool hi8  = (lane & 8)  != 0;
    float a  = hi16 ? v0 : v2;
    float ra = __shfl_xor_sync(0xffffffffu, a, 16);
    float x  = (hi16 ? v2 : v0) + ra;
    float bb = hi16 ? v1 : v3;
    float rb = __shfl_xor_sync(0xffffffffu, bb, 16);
    float y  = (hi16 ? v3 : v1) + rb;
    float c  = hi8 ? x : y;
    float rc = __shfl_xor_sync(0xffffffffu, c, 8);
    float z  = (hi8 ? y : x) + rc;
    z += __shfl_xor_sync(0xffffffffu, z, 4);
    z += __shfl_xor_sync(0xffffffffu, z, 2);
    z += __shfl_xor_sync(0xffffffffu, z, 1);
    return z;
}
__device__ __forceinline__ u32 smem_u32(const void* p) {
    u32 a;
    asm("{ .reg .u64 t; cvta.to.shared.u64 t, %1; cvt.u32.u64 %0, t; }"
        : "=r"(a) : "l"(p));
    return a;
}
__device__ __forceinline__ void mbar_init(u32 mbar, u32 cnt) {
    asm volatile("mbarrier.init.shared.b64 [%0], %1;" :: "r"(mbar), "r"(cnt) : "memory");
}
__device__ __forceinline__ void mbar_expect(u32 mbar, u32 bytes) {
    asm volatile("mbarrier.arrive.expect_tx.shared.b64 _, [%0], %1;"
                 :: "r"(mbar), "r"(bytes) : "memory");
}
__device__ __forceinline__ void bulk_g2s(u32 dst, const void* src, u32 bytes, u32 mbar) {
    asm volatile("cp.async.bulk.shared::cta.global.mbarrier::complete_tx::bytes "
                 "[%0], [%1], %2, [%3];"
                 :: "r"(dst), "l"(src), "r"(bytes), "r"(mbar) : "memory");
}
__device__ __forceinline__ void mbar_wait(u32 mbar, u32 parity) {
    asm volatile(
        "{\n\t.reg .pred P;\n"
        "W%=:\n\t"
        "mbarrier.try_wait.parity.acquire.cta.shared::cta.b64 P, [%0], %1, 0x989680;\n\t"
        "@P bra D%=;\n\t"
        "bra W%=;\n"
        "D%=:\n\t}"
        :: "r"(mbar), "r"(parity) : "memory");
}

extern __shared__ char smemc[];  // [ring bf16 | staging fp32 | mbar]

// read one fp32 row from staging, normalize (fp32), write bf16 row into ring.
__device__ __forceinline__ void norm_convert(const ulonglong2* stg_row,
                                             char* ring_row, int lane) {
    ulonglong2 v0 = stg_row[lane];
    ulonglong2 v1 = stg_row[lane + 32];
    ulonglong2 v2 = stg_row[lane + 64];
    ulonglong2 v3 = stg_row[lane + 96];
    u64 p0 = 0ull, p1 = 0ull, p2 = 0ull, p3 = 0ull;
    p0 = ffma2(v0.x, v0.x, p0); p1 = ffma2(v0.y, v0.y, p1);
    p2 = ffma2(v1.x, v1.x, p2); p3 = ffma2(v1.y, v1.y, p3);
    p0 = ffma2(v2.x, v2.x, p0); p1 = ffma2(v2.y, v2.y, p1);
    p2 = ffma2(v3.x, v3.x, p2); p3 = ffma2(v3.y, v3.y, p3);
    float s    = wred(hsum2(fadd2(fadd2(p0, p1), fadd2(p2, p3))));
    float invn = rsqrtf(s);
    u64 iv = pack2(invn, invn);

    ulonglong2 vg[4] = {v0, v1, v2, v3};
#pragma unroll
    for (int g = 0; g < 4; ++g) {
        u64 sx = fmul2(vg[g].x, iv);
        u64 sy = fmul2(vg[g].y, iv);
        float f0, f1, f2, f3;
        unpk2(sx, f0, f1);
        unpk2(sy, f2, f3);
        uint2 cc;
        cc.x = cvt2(f1, f0);
        cc.y = cvt2(f3, f2);
        *reinterpret_cast<uint2*>(ring_row + (g << 8) + (lane << 3)) = cc;
    }
}

// pair j -> partner distance d (j enumerates (d, ii) in the fixed order)
__device__ __forceinline__ int pair_d(int j) {
    return (j == 0) ? 10 : ((j == 19) ? 20 : (10 + ((j + 1) >> 1)));
}

__global__ void __launch_bounds__(NTHR, 1)
tcl_main(const float* __restrict__ hs, float* __restrict__ out) {
    const int seg  = blockIdx.x;
    const int b    = blockIdx.y;
    const int t0   = seg * SEGROWS;
    const int tEnd = (t0 + SEGROWS < SS) ? (t0 + SEGROWS) : SS;
    const int rEnd = (tEnd + HALO < SS) ? (tEnd + HALO) : SS;   // rows needed
    const int tid  = threadIdx.x;
    const int wid  = tid >> 5;
    const int lane = tid & 31;

    char* ring = smemc;
    const ulonglong2* stg = reinterpret_cast<const ulonglong2*>(smemc + RINGB);
    const char* gbase = reinterpret_cast<const char*>(hs) + (size_t)b * SS * ROWB;
    const u32 sbase = smem_u32(smemc);
    const u32 stgb  = sbase + RINGB;
    const u32 mbar  = sbase + MBAROFF;

    // ── prologue: staged copies of the first RING rows, convert to bf16 ──
    if (tid == 0) {
        mbar_init(mbar, 1);
        asm volatile("fence.proxy.async.shared::cta;" ::: "memory");
    }
    __syncthreads();

    int cid = 0;                                    // copy counter (parity)
    const int ringEnd = (t0 + RING < rEnd) ? (t0 + RING) : rEnd;
    {
        int ps = t0;
        int pe = (ps + CHUNK < ringEnd) ? (ps + CHUNK) : ringEnd;
        if (tid == 0) {
            mbar_expect(mbar, (u32)(pe - ps) * ROWB);
            bulk_g2s(stgb, gbase + (size_t)ps * ROWB, (u32)(pe - ps) * ROWB, mbar);
        }
        while (true) {
            mbar_wait(mbar, (u32)(cid & 1));
            cid++;
            for (int r = ps + wid; r < pe; r += NWARPS)
                norm_convert(stg + (size_t)(r - ps) * 128,
                             ring + (size_t)((r - t0) % RING) * RROWB, lane);
            __syncthreads();                        // staging consumed
            int ns = pe;
            int ne = (ns + CHUNK < ringEnd) ? (ns + CHUNK) : ringEnd;
            if (ns >= ne) break;
            if (tid == 0) {
                mbar_expect(mbar, (u32)(ne - ns) * ROWB);
                bulk_g2s(stgb, gbase + (size_t)ns * ROWB, (u32)(ne - ns) * ROWB, mbar);
            }
            ps = ns; pe = ne;
        }
    }
    __syncthreads();

    float accA = 0.f;   // adjacent sum (per-lane fp32 partials)
    float accD = 0.f;   // distant relu sum (octet-replicated)

    const int nsteps = (tEnd - t0 + CHUNK - 1) / CHUNK;

    for (int i = 0; i < nsteps; ++i) {
        const int c0     = t0 + CHUNK * i;
        const int rowEnd = (c0 + CHUNK < tEnd) ? (c0 + CHUNK) : tEnd;
        const int tt     = c0 + wid * TM;

        // ── Phase B: pairs for this 48-row chunk (24 warps × 2 rows) ────
        if (tt < rowEnd) {                       // warp-uniform; tiles 2-aligned
            int sb = (tt - t0) % RING;

            uint4 A[TM][2];
#pragma unroll
            for (int ii = 0; ii < TM; ++ii) {
                int sl = sb + ii; if (sl >= RING) sl -= RING;
                const uint4* rp = reinterpret_cast<const uint4*>(
                    ring + (size_t)sl * RROWB);
                A[ii][0] = rp[lane];
                A[ii][1] = rp[lane + 32];
            }

            // adjacent pair (tt, tt+1): both rows in registers
            {
                u32 a0 = 0, a1 = 0;
                a0 = hfma2b(A[0][0].x, A[1][0].x, a0);
                a1 = hfma2b(A[0][0].y, A[1][0].y, a1);
                a0 = hfma2b(A[0][0].z, A[1][0].z, a0);
                a1 = hfma2b(A[0][0].w, A[1][0].w, a1);
                a0 = hfma2b(A[0][1].x, A[1][1].x, a0);
                a1 = hfma2b(A[0][1].y, A[1][1].y, a1);
                a0 = hfma2b(A[0][1].z, A[1][1].z, a0);
                a1 = hfma2b(A[0][1].w, A[1][1].w, a1);
                accA += extbf(hadd2b(a0, a1));
            }

            // adjacent pair (tt+1, tt+2): partner row d = 2 from smem
            {
                int r = tt + TM;
                if (r < rEnd) {
                    int sl = sb + TM; if (sl >= RING) sl -= RING;
                    const uint4* rp = reinterpret_cast<const uint4*>(
                        ring + (size_t)sl * RROWB);
                    uint4 S0 = rp[lane];
                    uint4 S1 = rp[lane + 32];
                    u32 a0 = 0, a1 = 0;
                    a0 = hfma2b(A[1][0].x, S0.x, a0);
                    a1 = hfma2b(A[1][0].y, S0.y, a1);
                    a0 = hfma2b(A[1][0].z, S0.z, a0);
                    a1 = hfma2b(A[1][0].w, S0.w, a1);
                    a0 = hfma2b(A[1][1].x, S1.x, a0);
                    a1 = hfma2b(A[1][1].y, S1.y, a1);
                    a0 = hfma2b(A[1][1].z, S1.z, a0);
                    a1 = hfma2b(A[1][1].w, S1.w, a1);
                    accA += extbf(hadd2b(a0, a1));
                }
            }

            // distant pairs: 20 per-lane partial dots, then batched reduce
            float p[20];
#pragma unroll
            for (int j = 0; j < 20; ++j) p[j] = 0.f;

#pragma unroll
            for (int d = 10; d <= TM + HALO - 1; ++d) {
                int r = tt + d;
                if (r < rEnd) {                  // warp-uniform
                    int sl = sb + d; if (sl >= RING) sl -= RING;
                    const uint4* rp = reinterpret_cast<const uint4*>(
                        ring + (size_t)sl * RROWB);
                    uint4 S0 = rp[lane];
                    uint4 S1 = rp[lane + 32];
#pragma unroll
                    for (int ii = 0; ii < TM; ++ii) {
                        const int k = d - ii;
                        if (k >= 10 && k <= 19) {    // compile-time pruned
                            const int j = (d == 10) ? 0
                                        : ((d == 20) ? 19 : (2 * (d - 10) - 1 + ii));
                            u32 a0 = 0, a1 = 0;
                            a0 = hfma2b(A[ii][0].x, S0.x, a0);
                            a1 = hfma2b(A[ii][0].y, S0.y, a1);
                            a0 = hfma2b(A[ii][0].z, S0.z, a0);
                            a1 = hfma2b(A[ii][0].w, S0.w, a1);
                            a0 = hfma2b(A[ii][1].x, S1.x, a0);
                            a1 = hfma2b(A[ii][1].y, S1.y, a1);
                            a0 = hfma2b(A[ii][1].z, S1.z, a0);
                            a1 = hfma2b(A[ii][1].w, S1.w, a1);
                            p[j] = extbf(hadd2b(a0, a1));
                        }
                    }
                }
            }

            // batched reductions: 5 groups of 4 pairs, 6 shfl each
#pragma unroll
            for (int g = 0; g < 5; ++g) {
                float z = bfly4(p[4*g], p[4*g+1], p[4*g+2], p[4*g+3], lane);
                int jme = 4 * g + (lane >> 3);
                int dme = pair_d(jme);
                float contrib = (tt + dme < rEnd) ? fmaxf(0.5f - z, 0.f) : 0.f;
                accD += contrib;
            }
        }

        // ── wait for copy C_i (issued last step), convert into ring ─────
        if (i >= 1) {
            int cs = t0 + (RING - CHUNK) + CHUNK * i;   // t0 + 67 + 48i
            if (cs < rEnd) {
                mbar_wait(mbar, (u32)(cid & 1));
                cid++;
                int ce = (cs + CHUNK < rEnd) ? (cs + CHUNK) : rEnd;
                for (int r = cs + wid; r < ce; r += NWARPS)
                    norm_convert(stg + (size_t)(r - cs) * 128,
                                 ring + (size_t)((r - t0) % RING) * RROWB, lane);
            }
        }
        __syncthreads();

        // ── issue copy C_{i+1} into staging (consumed next step) ────────
        if (tid == 0) {
            int ns = t0 + (RING - CHUNK) + CHUNK * (i + 1);
            if (ns < rEnd) {
                int ne = (ns + CHUNK < rEnd) ? (ns + CHUNK) : rEnd;
                u32 bytes = (u32)(ne - ns) * ROWB;
                mbar_expect(mbar, bytes);
                bulk_g2s(stgb, gbase + (size_t)ns * ROWB, bytes, mbar);
            }
        }
    }

    // ── block combine + grid ticket reduction ───────────────────────────
    float aWarp = wred(accA);
    float dWarp = wred(accD) * 0.125f;   // each pair counted by 8 lanes

    __shared__ float rA[NWARPS], rD[NWARPS];
    __shared__ int   sLast;
    if (lane == 0) { rA[wid] = aWarp; rD[wid] = dWarp; }
    __syncthreads();
    if (tid == 0) {
        float sA = 0.f, sD = 0.f;
#pragma unroll
        for (int w = 0; w < NWARPS; ++w) { sA += rA[w]; sD += rD[w]; }
        g_part[b * NSEG + seg] = make_float2(sA, sD);
        __threadfence();
        unsigned t = atomicAdd(&g_count, 1u);
        sLast = (t == NBLK - 1);
    }
    __syncthreads();

    if (sLast && tid < 32) {
        __threadfence();
        const float* gp = reinterpret_cast<const float*>(g_part);
        float a = 0.f, dd = 0.f;
        for (int i = tid; i < NBLK; i += 32) {
            a  += __ldcg(gp + 2 * i);
            dd += __ldcg(gp + 2 * i + 1);
        }
        a  = wred(a);
        dd = wred(dd);
        if (tid == 0) {
            float adj  = 1.f - a / ((float)NB * (float)(SS - 1));
            float dist = dd / ((float)NB * (float)CNT_DIST);
            out[0] = adj + dist;
            g_count = 0;                      // reset for next graph replay
        }
    }
}

extern "C" void kernel_launch(void* const* d_in, const int* in_sizes, int n_in,
                              void* d_out, int out_size) {
    (void)in_sizes; (void)n_in; (void)out_size;
    const float* hs = (const float*)d_in[0];

    cudaFuncSetAttribute(tcl_main, cudaFuncAttributeMaxDynamicSharedMemorySize,
                         SMEMSZ);

    dim3 grid(NSEG, NB);
    tcl_main<<<grid, NTHR, SMEMSZ>>>(hs, (float*)d_out);
}